// round 2
// baseline (speedup 1.0000x reference)
#include <cuda_runtime.h>

#define BB 16
#define NN 4096
#define CC 64
#define SS 1024
#define KNB 32

// scratch: ball-query indices
__device__ int g_idx[BB * SS * KNB];

// ---------------------------------------------------------------------------
// Kernel 1: farthest point sampling. One block per batch. Points + running
// min-distances live in registers (4 per thread). Exact (non-FMA) distance
// math to match reference rounding; argmax picks the first max index.
// ---------------------------------------------------------------------------
__global__ __launch_bounds__(1024) void fps_kernel(const float* __restrict__ xyz,
                                                   float* __restrict__ out_xyz) {
    const int b = blockIdx.x;
    const float* x = xyz + (size_t)b * NN * 3;
    const int tid = threadIdx.x;

    float px[4], py[4], pz[4], dmin[4];
#pragma unroll
    for (int k = 0; k < 4; k++) {
        int j = tid * 4 + k;
        px[k] = x[j * 3 + 0];
        py[k] = x[j * 3 + 1];
        pz[k] = x[j * 3 + 2];
        dmin[k] = 1e10f;
    }

    __shared__ float rv[32];
    __shared__ int ri[32];
    __shared__ int sfar;

    int far = 0;
    for (int i = 0; i < SS; i++) {
        float cx = x[far * 3 + 0];
        float cy = x[far * 3 + 1];
        float cz = x[far * 3 + 2];
        if (tid == 0) {
            float* o = out_xyz + ((size_t)b * SS + i) * 3;
            o[0] = cx; o[1] = cy; o[2] = cz;
        }
        float best = -1.0f;
        int bi = 0;
#pragma unroll
        for (int k = 0; k < 4; k++) {
            float dx = px[k] - cx;
            float dy = py[k] - cy;
            float dz = pz[k] - cz;
            float d = __fadd_rn(__fadd_rn(__fmul_rn(dx, dx), __fmul_rn(dy, dy)),
                                __fmul_rn(dz, dz));
            float dm = fminf(dmin[k], d);
            dmin[k] = dm;
            if (dm > best) { best = dm; bi = tid * 4 + k; }
        }
        // warp argmax (first index wins ties)
#pragma unroll
        for (int off = 16; off; off >>= 1) {
            float ov = __shfl_down_sync(0xffffffffu, best, off);
            int oi = __shfl_down_sync(0xffffffffu, bi, off);
            if (ov > best || (ov == best && oi < bi)) { best = ov; bi = oi; }
        }
        int wid = tid >> 5, lane = tid & 31;
        if (lane == 0) { rv[wid] = best; ri[wid] = bi; }
        __syncthreads();
        if (wid == 0) {
            best = rv[lane];
            bi = ri[lane];
#pragma unroll
            for (int off = 16; off; off >>= 1) {
                float ov = __shfl_down_sync(0xffffffffu, best, off);
                int oi = __shfl_down_sync(0xffffffffu, bi, off);
                if (ov > best || (ov == best && oi < bi)) { best = ov; bi = oi; }
            }
            if (lane == 0) sfar = bi;
        }
        __syncthreads();
        far = sfar;
    }
}

// ---------------------------------------------------------------------------
// Kernel 2: ball query. One warp per (b,s). Collect the first K indices (in
// ascending order) with d2 <= r^2; pad with the first hit.
// ---------------------------------------------------------------------------
__global__ __launch_bounds__(256) void qb_kernel(const float* __restrict__ xyz,
                                                 const float* __restrict__ new_xyz) {
    const int gw = (blockIdx.x * blockDim.x + threadIdx.x) >> 5;
    const int lane = threadIdx.x & 31;
    if (gw >= BB * SS) return;
    const int b = gw >> 10;
    const float* x = xyz + (size_t)b * NN * 3;
    const float cx = new_xyz[gw * 3 + 0];
    const float cy = new_xyz[gw * 3 + 1];
    const float cz = new_xyz[gw * 3 + 2];
    int* o = g_idx + (size_t)gw * KNB;

    const float r2 = 0.04f;  // f32(0.2*0.2 in double)
    int cnt = 0;
    int first = 0;
    bool have = false;
    for (int j0 = 0; j0 < NN; j0 += 32) {
        int j = j0 + lane;
        float dx = x[j * 3 + 0] - cx;
        float dy = x[j * 3 + 1] - cy;
        float dz = x[j * 3 + 2] - cz;
        float d = __fadd_rn(__fadd_rn(__fmul_rn(dx, dx), __fmul_rn(dy, dy)),
                            __fmul_rn(dz, dz));
        bool in = (d <= r2);
        unsigned m = __ballot_sync(0xffffffffu, in);
        if (!have && m) { first = j0 + __ffs(m) - 1; have = true; }
        int pre = __popc(m & ((1u << lane) - 1u));
        if (in) {
            int p = cnt + pre;
            if (p < KNB) o[p] = j;
        }
        cnt += __popc(m);
        if (cnt >= KNB) break;
    }
    for (int p = cnt + lane; p < KNB; p += 32) o[p] = first;
}

// ---------------------------------------------------------------------------
// Kernel 3: gather + 3-layer MLP + maxpool over K. One block per (b,s).
// Activations staged in shared (broadcast reads), weights via L1/L2.
// Stage 2 keeps all 32 rows in registers and max-pools in-register.
// ---------------------------------------------------------------------------
__global__ __launch_bounds__(128) void mlp_kernel(
    const float* __restrict__ xyz, const float* __restrict__ points,
    const float* __restrict__ new_xyz,
    const float* __restrict__ w0, const float* __restrict__ b0,
    const float* __restrict__ w1, const float* __restrict__ b1,
    const float* __restrict__ w2, const float* __restrict__ b2,
    float* __restrict__ out_points) {
    const int gw = blockIdx.x;  // b*S + s
    const int b = gw >> 10;
    const int tid = threadIdx.x;
    const int lane = tid & 31, wid = tid >> 5;

    __shared__ int sidx[KNB];
    __shared__ float sc[3];
    __shared__ float sX[KNB * 67];
    __shared__ float sH[KNB * 64];
    __shared__ float sG[KNB * 64];

    if (tid < KNB) sidx[tid] = g_idx[(size_t)gw * KNB + tid];
    if (tid < 3) sc[tid] = new_xyz[gw * 3 + tid];
    __syncthreads();

    // gather: rows = neighbors; cols 0..63 = point feats, 64..66 = rel xyz
    for (int r = wid; r < KNB; r += 4) {
        int id = sidx[r];
        const float* p = points + ((size_t)b * NN + id) * CC;
        sX[r * 67 + lane] = p[lane];
        sX[r * 67 + 32 + lane] = p[32 + lane];
        if (lane < 3)
            sX[r * 67 + 64 + lane] = xyz[((size_t)b * NN + id) * 3 + lane] - sc[lane];
    }
    __syncthreads();

    // stage 0: 67 -> 64
    {
        const int f = tid & 63;
        const int rh = tid >> 6;  // two half-row groups of 16
        float acc[16];
#pragma unroll
        for (int t = 0; t < 16; t++) acc[t] = 0.0f;
        for (int c = 0; c < 67; c++) {
            float w = w0[c * 64 + f];
#pragma unroll
            for (int t = 0; t < 16; t++) acc[t] += sX[(rh * 16 + t) * 67 + c] * w;
        }
        float bb = b0[f];
#pragma unroll
        for (int t = 0; t < 16; t++)
            sH[(rh * 16 + t) * 64 + f] = fmaxf(acc[t] + bb, 0.0f);
    }
    __syncthreads();

    // stage 1: 64 -> 64
    {
        const int f = tid & 63;
        const int rh = tid >> 6;
        float acc[16];
#pragma unroll
        for (int t = 0; t < 16; t++) acc[t] = 0.0f;
        for (int c = 0; c < 64; c++) {
            float w = w1[c * 64 + f];
#pragma unroll
            for (int t = 0; t < 16; t++) acc[t] += sH[(rh * 16 + t) * 64 + c] * w;
        }
        float bb = b1[f];
#pragma unroll
        for (int t = 0; t < 16; t++)
            sG[(rh * 16 + t) * 64 + f] = fmaxf(acc[t] + bb, 0.0f);
    }
    __syncthreads();

    // stage 2: 64 -> 128, fused maxpool over the 32 rows
    {
        const int f = tid;  // 0..127
        float acc[32];
#pragma unroll
        for (int r = 0; r < 32; r++) acc[r] = 0.0f;
        for (int c = 0; c < 64; c++) {
            float w = w2[c * 128 + f];
#pragma unroll
            for (int r = 0; r < 32; r++) acc[r] += sG[r * 64 + c] * w;
        }
        float bb = b2[f];
        float m = 0.0f;
#pragma unroll
        for (int r = 0; r < 32; r++) m = fmaxf(m, fmaxf(acc[r] + bb, 0.0f));
        out_points[(size_t)gw * 128 + f] = m;
    }
}

extern "C" void kernel_launch(void* const* d_in, const int* in_sizes, int n_in,
                              void* d_out, int out_size) {
    const float* xyz = (const float*)d_in[0];
    const float* points = (const float*)d_in[1];
    const float* w0 = (const float*)d_in[2];
    const float* b0 = (const float*)d_in[3];
    const float* w1 = (const float*)d_in[4];
    const float* b1 = (const float*)d_in[5];
    const float* w2 = (const float*)d_in[6];
    const float* b2 = (const float*)d_in[7];

    float* out = (float*)d_out;
    float* new_xyz = out;                      // [B, S, 3]
    float* new_points = out + BB * SS * 3;     // [B, S, 128]

    fps_kernel<<<BB, 1024>>>(xyz, new_xyz);
    qb_kernel<<<(BB * SS * 32 + 255) / 256, 256>>>(xyz, new_xyz);
    mlp_kernel<<<BB * SS, 128>>>(xyz, points, new_xyz,
                                 w0, b0, w1, b1, w2, b2, new_points);
}

// round 4
// speedup vs baseline: 1.7164x; 1.7164x over previous
#include <cuda_runtime.h>

#define BB 16
#define NN 4096
#define CC 64
#define SS 1024
#define KNB 32

// scratch: ball-query indices
__device__ int g_idx[BB * SS * KNB];

// ---------------------------------------------------------------------------
// packed f32x2 helpers (sm_100+)
// ---------------------------------------------------------------------------
__device__ __forceinline__ unsigned long long pack2(float a, float b) {
    unsigned long long r;
    asm("mov.b64 %0, {%1, %2};" : "=l"(r) : "f"(a), "f"(b));
    return r;
}
__device__ __forceinline__ void unpack2(unsigned long long v, float& a, float& b) {
    asm("mov.b64 {%0, %1}, %2;" : "=f"(a), "=f"(b) : "l"(v));
}
__device__ __forceinline__ void ffma2(unsigned long long& d, unsigned long long a,
                                      unsigned long long b) {
    asm("fma.rn.f32x2 %0, %1, %2, %0;" : "+l"(d) : "l"(a), "l"(b));
}

// ---------------------------------------------------------------------------
// Kernel 1: farthest point sampling. One block (256 thr) per batch, 16 points
// per thread in registers. Exact (non-FMA) distance math to match reference
// rounding. Argmax: REDUX warp max + ballot (first lane = first index), then
// one syncthreads over a parity-double-buffered 8-entry packed-key array.
// ---------------------------------------------------------------------------
__global__ __launch_bounds__(256) void fps_kernel(const float* __restrict__ xyz,
                                                  float* __restrict__ out_xyz) {
    const int b = blockIdx.x;
    const float* x = xyz + (size_t)b * NN * 3;
    const int tid = threadIdx.x;
    const int lane = tid & 31, wid = tid >> 5;

    float px[16], py[16], pz[16], dmin[16];
#pragma unroll
    for (int k = 0; k < 16; k++) {
        int j = tid * 16 + k;
        px[k] = x[j * 3 + 0];
        py[k] = x[j * 3 + 1];
        pz[k] = x[j * 3 + 2];
        dmin[k] = 1e10f;
    }

    __shared__ unsigned long long sred[2][8];

    int far = 0;
    for (int i = 0; i < SS; i++) {
        float cx = x[far * 3 + 0];
        float cy = x[far * 3 + 1];
        float cz = x[far * 3 + 2];
        if (tid == 0) {
            float* o = out_xyz + ((size_t)b * SS + i) * 3;
            o[0] = cx; o[1] = cy; o[2] = cz;
        }
        float bv = -1.0f;
        int bk = 0;
#pragma unroll
        for (int k = 0; k < 16; k++) {
            float dx = px[k] - cx;
            float dy = py[k] - cy;
            float dz = pz[k] - cz;
            float d = __fadd_rn(__fadd_rn(__fmul_rn(dx, dx), __fmul_rn(dy, dy)),
                                __fmul_rn(dz, dz));
            float dm = fminf(dmin[k], d);
            dmin[k] = dm;
            if (dm > bv) { bv = dm; bk = k; }   // first (lowest k) wins ties
        }
        unsigned vb = __float_as_uint(bv);               // dmin >= 0: bits monotone
        unsigned wm = __reduce_max_sync(0xffffffffu, vb);
        unsigned bal = __ballot_sync(0xffffffffu, vb == wm);
        int src = __ffs(bal) - 1;                        // lowest lane = lowest index
        int widx = __shfl_sync(0xffffffffu, tid * 16 + bk, src);
        if (lane == 0)
            sred[i & 1][wid] =
                ((unsigned long long)wm << 32) | (unsigned)(~(unsigned)widx);
        __syncthreads();
        unsigned long long bestk = sred[i & 1][0];
#pragma unroll
        for (int w = 1; w < 8; w++) {
            unsigned long long v = sred[i & 1][w];
            bestk = (v > bestk) ? v : bestk;             // tie -> larger ~idx = smaller idx
        }
        far = (int)(~(unsigned)bestk);
    }
}

// ---------------------------------------------------------------------------
// Kernel 2: ball query. One warp per (b,s). First K indices (ascending)
// with d2 <= r^2; pad with first hit. Exact math to match reference.
// ---------------------------------------------------------------------------
__global__ __launch_bounds__(256) void qb_kernel(const float* __restrict__ xyz,
                                                 const float* __restrict__ new_xyz) {
    const int gw = (blockIdx.x * blockDim.x + threadIdx.x) >> 5;
    const int lane = threadIdx.x & 31;
    if (gw >= BB * SS) return;
    const int b = gw >> 10;
    const float* x = xyz + (size_t)b * NN * 3;
    const float cx = new_xyz[gw * 3 + 0];
    const float cy = new_xyz[gw * 3 + 1];
    const float cz = new_xyz[gw * 3 + 2];
    int* o = g_idx + (size_t)gw * KNB;

    const float r2 = 0.04f;
    int cnt = 0;
    int first = 0;
    bool have = false;
    for (int j0 = 0; j0 < NN; j0 += 32) {
        int j = j0 + lane;
        float dx = x[j * 3 + 0] - cx;
        float dy = x[j * 3 + 1] - cy;
        float dz = x[j * 3 + 2] - cz;
        float d = __fadd_rn(__fadd_rn(__fmul_rn(dx, dx), __fmul_rn(dy, dy)),
                            __fmul_rn(dz, dz));
        bool in = (d <= r2);
        unsigned m = __ballot_sync(0xffffffffu, in);
        if (!have && m) { first = j0 + __ffs(m) - 1; have = true; }
        int pre = __popc(m & ((1u << lane) - 1u));
        if (in) {
            int p = cnt + pre;
            if (p < KNB) o[p] = j;
        }
        cnt += __popc(m);
        if (cnt >= KNB) break;
    }
    for (int p = cnt + lane; p < KNB; p += 32) o[p] = first;
}

// ---------------------------------------------------------------------------
// Kernel 3: gather + 3-layer MLP + maxpool, packed f32x2 FMA.
// Activations column-major [c][r] with pad 36 (stride 144B = 9x16B) and
// 16B-aligned bases for ulonglong2 loads. One block (128 thr) per (b,s).
// ---------------------------------------------------------------------------
__global__ __launch_bounds__(128) void mlp_kernel(
    const float* __restrict__ xyz, const float* __restrict__ points,
    const float* __restrict__ new_xyz,
    const float* __restrict__ w0, const float* __restrict__ b0,
    const float* __restrict__ w1, const float* __restrict__ b1,
    const float* __restrict__ w2, const float* __restrict__ b2,
    float* __restrict__ out_points) {
    const int gw = blockIdx.x;  // b*S + s
    const int b = gw >> 10;
    const int tid = threadIdx.x;
    const int lane = tid & 31, wid = tid >> 5;

    __shared__ __align__(16) float sX[67 * 36];  // [c][r], pad 36
    __shared__ __align__(16) float sH[64 * 36];
    __shared__ __align__(16) float sG[64 * 36];
    __shared__ int sidx[KNB];
    __shared__ float sc[3];

    if (tid < KNB) sidx[tid] = g_idx[(size_t)gw * KNB + tid];
    if (tid < 3) sc[tid] = new_xyz[gw * 3 + tid];
    __syncthreads();

    // gather: warp handles row r (coalesced LDG over features), col-major STS
    for (int r = wid; r < KNB; r += 4) {
        int id = sidx[r];
        const float* p = points + ((size_t)b * NN + id) * CC;
        float v0 = p[lane];
        float v1 = p[32 + lane];
        sX[lane * 36 + r] = v0;
        sX[(32 + lane) * 36 + r] = v1;
        if (lane < 3)
            sX[(64 + lane) * 36 + r] =
                xyz[((size_t)b * NN + id) * 3 + lane] - sc[lane];
    }
    __syncthreads();

    // stage 0: 67 -> 64 ; thread = (feature f, row-half rh) ; 16 rows packed
    {
        const int f = tid & 63;
        const int rh = tid >> 6;
        unsigned long long acc[8];
#pragma unroll
        for (int t = 0; t < 8; t++) acc[t] = pack2(0.0f, 0.0f);
        for (int c = 0; c < 67; c++) {
            float w = w0[c * 64 + f];
            unsigned long long ww = pack2(w, w);
            const ulonglong2* xp = (const ulonglong2*)(sX + c * 36 + rh * 16);
            ulonglong2 u0 = xp[0], u1 = xp[1], u2 = xp[2], u3 = xp[3];
            ffma2(acc[0], u0.x, ww); ffma2(acc[1], u0.y, ww);
            ffma2(acc[2], u1.x, ww); ffma2(acc[3], u1.y, ww);
            ffma2(acc[4], u2.x, ww); ffma2(acc[5], u2.y, ww);
            ffma2(acc[6], u3.x, ww); ffma2(acc[7], u3.y, ww);
        }
        float bb = b0[f];
#pragma unroll
        for (int t = 0; t < 8; t++) {
            float a0, a1;
            unpack2(acc[t], a0, a1);
            a0 = fmaxf(a0 + bb, 0.0f);
            a1 = fmaxf(a1 + bb, 0.0f);
            *(float2*)(sH + f * 36 + rh * 16 + 2 * t) = make_float2(a0, a1);
        }
    }
    __syncthreads();

    // stage 1: 64 -> 64
    {
        const int f = tid & 63;
        const int rh = tid >> 6;
        unsigned long long acc[8];
#pragma unroll
        for (int t = 0; t < 8; t++) acc[t] = pack2(0.0f, 0.0f);
        for (int c = 0; c < 64; c++) {
            float w = w1[c * 64 + f];
            unsigned long long ww = pack2(w, w);
            const ulonglong2* xp = (const ulonglong2*)(sH + c * 36 + rh * 16);
            ulonglong2 u0 = xp[0], u1 = xp[1], u2 = xp[2], u3 = xp[3];
            ffma2(acc[0], u0.x, ww); ffma2(acc[1], u0.y, ww);
            ffma2(acc[2], u1.x, ww); ffma2(acc[3], u1.y, ww);
            ffma2(acc[4], u2.x, ww); ffma2(acc[5], u2.y, ww);
            ffma2(acc[6], u3.x, ww); ffma2(acc[7], u3.y, ww);
        }
        float bb = b1[f];
#pragma unroll
        for (int t = 0; t < 8; t++) {
            float a0, a1;
            unpack2(acc[t], a0, a1);
            a0 = fmaxf(a0 + bb, 0.0f);
            a1 = fmaxf(a1 + bb, 0.0f);
            *(float2*)(sG + f * 36 + rh * 16 + 2 * t) = make_float2(a0, a1);
        }
    }
    __syncthreads();

    // stage 2: 64 -> 128, fused maxpool over 32 rows (all packed)
    {
        const int f = tid;  // 0..127
        unsigned long long acc[16];
#pragma unroll
        for (int t = 0; t < 16; t++) acc[t] = pack2(0.0f, 0.0f);
        for (int c = 0; c < 64; c++) {
            float w = w2[c * 128 + f];
            unsigned long long ww = pack2(w, w);
            const ulonglong2* gp = (const ulonglong2*)(sG + c * 36);
#pragma unroll
            for (int q = 0; q < 4; q++) {
                ulonglong2 ua = gp[2 * q];
                ulonglong2 ub = gp[2 * q + 1];
                ffma2(acc[4 * q + 0], ua.x, ww);
                ffma2(acc[4 * q + 1], ua.y, ww);
                ffma2(acc[4 * q + 2], ub.x, ww);
                ffma2(acc[4 * q + 3], ub.y, ww);
            }
        }
        float bb = b2[f];
        float m = 0.0f;
#pragma unroll
        for (int t = 0; t < 16; t++) {
            float a0, a1;
            unpack2(acc[t], a0, a1);
            m = fmaxf(m, fmaxf(a0 + bb, 0.0f));
            m = fmaxf(m, fmaxf(a1 + bb, 0.0f));
        }
        out_points[(size_t)gw * 128 + f] = m;
    }
}

extern "C" void kernel_launch(void* const* d_in, const int* in_sizes, int n_in,
                              void* d_out, int out_size) {
    const float* xyz = (const float*)d_in[0];
    const float* points = (const float*)d_in[1];
    const float* w0 = (const float*)d_in[2];
    const float* b0 = (const float*)d_in[3];
    const float* w1 = (const float*)d_in[4];
    const float* b1 = (const float*)d_in[5];
    const float* w2 = (const float*)d_in[6];
    const float* b2 = (const float*)d_in[7];

    float* out = (float*)d_out;
    float* new_xyz = out;                   // [B, S, 3]
    float* new_points = out + BB * SS * 3;  // [B, S, 128]

    fps_kernel<<<BB, 256>>>(xyz, new_xyz);
    qb_kernel<<<(BB * SS * 32 + 255) / 256, 256>>>(xyz, new_xyz);
    mlp_kernel<<<BB * SS, 128>>>(xyz, points, new_xyz,
                                 w0, b0, w1, b1, w2, b2, new_points);
}

// round 5
// speedup vs baseline: 2.2429x; 1.3068x over previous
#include <cuda_runtime.h>

#define BB 16
#define NN 4096
#define CC 64
#define SS 1024
#define KNB 32

__device__ int g_idx[BB * SS * KNB];

// ---------------------------------------------------------------------------
// packed f32x2 helpers (sm_100+). Per-lane IEEE rn => bit-identical to scalar.
// ---------------------------------------------------------------------------
__device__ __forceinline__ unsigned long long pack2(float a, float b) {
    unsigned long long r;
    asm("mov.b64 %0, {%1, %2};" : "=l"(r) : "f"(a), "f"(b));
    return r;
}
__device__ __forceinline__ void unpack2(unsigned long long v, float& a, float& b) {
    asm("mov.b64 {%0, %1}, %2;" : "=f"(a), "=f"(b) : "l"(v));
}
__device__ __forceinline__ void ffma2(unsigned long long& d, unsigned long long a,
                                      unsigned long long b) {
    asm("fma.rn.f32x2 %0, %1, %2, %0;" : "+l"(d) : "l"(a), "l"(b));
}
__device__ __forceinline__ unsigned long long sub2(unsigned long long a,
                                                   unsigned long long b) {
    unsigned long long r;
    asm("sub.rn.f32x2 %0, %1, %2;" : "=l"(r) : "l"(a), "l"(b));
    return r;
}
__device__ __forceinline__ unsigned long long mul2(unsigned long long a,
                                                   unsigned long long b) {
    unsigned long long r;
    asm("mul.rn.f32x2 %0, %1, %2;" : "=l"(r) : "l"(a), "l"(b));
    return r;
}
__device__ __forceinline__ unsigned long long add2(unsigned long long a,
                                                   unsigned long long b) {
    unsigned long long r;
    asm("add.rn.f32x2 %0, %1, %2;" : "=l"(r) : "l"(a), "l"(b));
    return r;
}
__device__ __forceinline__ unsigned long long u64max(unsigned long long a,
                                                     unsigned long long b) {
    return a > b ? a : b;
}

// ---------------------------------------------------------------------------
// Kernel 1: FPS. One block (256 thr) per batch; 16 points/thread in packed
// registers. Packed f32x2 distance math (bit-identical rounding to scalar),
// value-only argmax: REDUX + ballot -> elected lane; equality search for k;
// cross-warp 64-bit key (val<<32 | 4095-gidx) tree-reduced from shared.
// ---------------------------------------------------------------------------
__global__ __launch_bounds__(256) void fps_kernel(const float* __restrict__ xyz,
                                                  float* __restrict__ out_xyz) {
    const int b = blockIdx.x;
    const float* x = xyz + (size_t)b * NN * 3;
    const int tid = threadIdx.x;
    const int lane = tid & 31, wid = tid >> 5;

    unsigned long long pxp[8], pyp[8], pzp[8];
    float dmin[16];
#pragma unroll
    for (int p = 0; p < 8; p++) {
        int j = tid * 16 + 2 * p;
        pxp[p] = pack2(x[j * 3 + 0], x[j * 3 + 3]);
        pyp[p] = pack2(x[j * 3 + 1], x[j * 3 + 4]);
        pzp[p] = pack2(x[j * 3 + 2], x[j * 3 + 5]);
        dmin[2 * p] = 1e10f;
        dmin[2 * p + 1] = 1e10f;
    }

    __shared__ unsigned long long skey[2][8];

    float ccx = x[0], ccy = x[1], ccz = x[2];

    for (int i = 0; i < SS; i++) {
        const int par = i & 1;
        if (tid == 0) {
            float* o = out_xyz + ((size_t)b * SS + i) * 3;
            o[0] = ccx; o[1] = ccy; o[2] = ccz;
        }
        unsigned long long cx2 = pack2(ccx, ccx);
        unsigned long long cy2 = pack2(ccy, ccy);
        unsigned long long cz2 = pack2(ccz, ccz);

        float bva = -1.0f, bvb = -1.0f;
#pragma unroll
        for (int p = 0; p < 8; p++) {
            unsigned long long sx = sub2(pxp[p], cx2);
            unsigned long long sy = sub2(pyp[p], cy2);
            unsigned long long sz = sub2(pzp[p], cz2);
            unsigned long long dd =
                add2(add2(mul2(sx, sx), mul2(sy, sy)), mul2(sz, sz));
            float d0, d1;
            unpack2(dd, d0, d1);
            dmin[2 * p] = fminf(dmin[2 * p], d0);
            dmin[2 * p + 1] = fminf(dmin[2 * p + 1], d1);
            bva = fmaxf(bva, dmin[2 * p]);
            bvb = fmaxf(bvb, dmin[2 * p + 1]);
        }
        float bv = fmaxf(bva, bvb);

        unsigned vb = __float_as_uint(bv);              // nonneg: bits monotone
        unsigned wm = __reduce_max_sync(0xffffffffu, vb);
        unsigned bal = __ballot_sync(0xffffffffu, vb == wm);
        int src = __ffs(bal) - 1;                       // lowest lane = lowest idx

        // all lanes search (only src's result used); descending -> lowest k wins
        int ck = 0;
#pragma unroll
        for (int k = 15; k >= 1; k--)
            if (__float_as_uint(dmin[k]) == wm) ck = k;

        int gidx = (wid * 32 + src) * 16 + __shfl_sync(0xffffffffu, ck, src);
        if (lane == 0)
            skey[par][wid] =
                ((unsigned long long)wm << 32) | (unsigned)(4095 - gidx);
        __syncthreads();

        unsigned long long k0 = skey[par][0], k1 = skey[par][1];
        unsigned long long k2 = skey[par][2], k3 = skey[par][3];
        unsigned long long k4 = skey[par][4], k5 = skey[par][5];
        unsigned long long k6 = skey[par][6], k7 = skey[par][7];
        unsigned long long m0 = u64max(u64max(k0, k1), u64max(k2, k3));
        unsigned long long m1 = u64max(u64max(k4, k5), u64max(k6, k7));
        unsigned long long mk = u64max(m0, m1);
        int far = 4095 - (int)(unsigned)mk;

        ccx = x[far * 3 + 0];
        ccy = x[far * 3 + 1];
        ccz = x[far * 3 + 2];
    }
}

// ---------------------------------------------------------------------------
// Kernel 2: ball query (unchanged).
// ---------------------------------------------------------------------------
__global__ __launch_bounds__(256) void qb_kernel(const float* __restrict__ xyz,
                                                 const float* __restrict__ new_xyz) {
    const int gw = (blockIdx.x * blockDim.x + threadIdx.x) >> 5;
    const int lane = threadIdx.x & 31;
    if (gw >= BB * SS) return;
    const int b = gw >> 10;
    const float* x = xyz + (size_t)b * NN * 3;
    const float cx = new_xyz[gw * 3 + 0];
    const float cy = new_xyz[gw * 3 + 1];
    const float cz = new_xyz[gw * 3 + 2];
    int* o = g_idx + (size_t)gw * KNB;

    const float r2 = 0.04f;
    int cnt = 0;
    int first = 0;
    bool have = false;
    for (int j0 = 0; j0 < NN; j0 += 32) {
        int j = j0 + lane;
        float dx = x[j * 3 + 0] - cx;
        float dy = x[j * 3 + 1] - cy;
        float dz = x[j * 3 + 2] - cz;
        float d = __fadd_rn(__fadd_rn(__fmul_rn(dx, dx), __fmul_rn(dy, dy)),
                            __fmul_rn(dz, dz));
        bool in = (d <= r2);
        unsigned m = __ballot_sync(0xffffffffu, in);
        if (!have && m) { first = j0 + __ffs(m) - 1; have = true; }
        int pre = __popc(m & ((1u << lane) - 1u));
        if (in) {
            int p = cnt + pre;
            if (p < KNB) o[p] = j;
        }
        cnt += __popc(m);
        if (cnt >= KNB) break;
    }
    for (int p = cnt + lane; p < KNB; p += 32) o[p] = first;
}

// ---------------------------------------------------------------------------
// Kernel 3: gather + MLP + maxpool, packed f32x2, 2 features per thread
// (halves LDS issue). Stage1 output aliases sX. Bit-exact accumulation order.
// ---------------------------------------------------------------------------
__global__ __launch_bounds__(128) void mlp_kernel(
    const float* __restrict__ xyz, const float* __restrict__ points,
    const float* __restrict__ new_xyz,
    const float* __restrict__ w0, const float* __restrict__ b0,
    const float* __restrict__ w1, const float* __restrict__ b1,
    const float* __restrict__ w2, const float* __restrict__ b2,
    float* __restrict__ out_points) {
    const int gw = blockIdx.x;  // b*S + s
    const int b = gw >> 10;
    const int tid = threadIdx.x;
    const int lane = tid & 31, wid = tid >> 5;

    __shared__ __align__(16) float sX[67 * 36];  // stage0 in; stage1 out (alias)
    __shared__ __align__(16) float sH[64 * 36];  // stage0 out / stage1 in
    __shared__ __align__(16) float smax[2][128];
    __shared__ int sidx[KNB];
    __shared__ float sc[3];

    if (tid < KNB) sidx[tid] = g_idx[(size_t)gw * KNB + tid];
    if (tid < 3) sc[tid] = new_xyz[gw * 3 + tid];
    __syncthreads();

    // gather (col-major [c][r], stride 36)
    for (int r = wid; r < KNB; r += 4) {
        int id = sidx[r];
        const float* p = points + ((size_t)b * NN + id) * CC;
        float v0 = p[lane];
        float v1 = p[32 + lane];
        sX[lane * 36 + r] = v0;
        sX[(32 + lane) * 36 + r] = v1;
        if (lane < 3)
            sX[(64 + lane) * 36 + r] =
                xyz[((size_t)b * NN + id) * 3 + lane] - sc[lane];
    }
    __syncthreads();

    // stage 0: 67 -> 64. thread = (feature-pair fp, row-octet rh)
    {
        const int fp = tid & 31;        // features fp, fp+32
        const int rh = tid >> 5;        // rows rh*8 .. rh*8+7
        unsigned long long acc[8];
#pragma unroll
        for (int t = 0; t < 8; t++) acc[t] = 0ull;
#pragma unroll 4
        for (int c = 0; c < 67; c++) {
            float wa = w0[c * 64 + fp];
            float wb = w0[c * 64 + fp + 32];
            unsigned long long wa2 = pack2(wa, wa);
            unsigned long long wb2 = pack2(wb, wb);
            const ulonglong2* xp = (const ulonglong2*)(sX + c * 36 + rh * 8);
            ulonglong2 u0 = xp[0], u1 = xp[1];
            ffma2(acc[0], u0.x, wa2); ffma2(acc[1], u0.y, wa2);
            ffma2(acc[2], u1.x, wa2); ffma2(acc[3], u1.y, wa2);
            ffma2(acc[4], u0.x, wb2); ffma2(acc[5], u0.y, wb2);
            ffma2(acc[6], u1.x, wb2); ffma2(acc[7], u1.y, wb2);
        }
        float ba = b0[fp], bbv = b0[fp + 32];
#pragma unroll
        for (int t = 0; t < 4; t++) {
            float a0, a1;
            unpack2(acc[t], a0, a1);
            *(float2*)(sH + fp * 36 + rh * 8 + 2 * t) =
                make_float2(fmaxf(a0 + ba, 0.0f), fmaxf(a1 + ba, 0.0f));
            unpack2(acc[4 + t], a0, a1);
            *(float2*)(sH + (fp + 32) * 36 + rh * 8 + 2 * t) =
                make_float2(fmaxf(a0 + bbv, 0.0f), fmaxf(a1 + bbv, 0.0f));
        }
    }
    __syncthreads();

    // stage 1: 64 -> 64 (reads sH, writes sX alias)
    {
        const int fp = tid & 31;
        const int rh = tid >> 5;
        unsigned long long acc[8];
#pragma unroll
        for (int t = 0; t < 8; t++) acc[t] = 0ull;
#pragma unroll 4
        for (int c = 0; c < 64; c++) {
            float wa = w1[c * 64 + fp];
            float wb = w1[c * 64 + fp + 32];
            unsigned long long wa2 = pack2(wa, wa);
            unsigned long long wb2 = pack2(wb, wb);
            const ulonglong2* xp = (const ulonglong2*)(sH + c * 36 + rh * 8);
            ulonglong2 u0 = xp[0], u1 = xp[1];
            ffma2(acc[0], u0.x, wa2); ffma2(acc[1], u0.y, wa2);
            ffma2(acc[2], u1.x, wa2); ffma2(acc[3], u1.y, wa2);
            ffma2(acc[4], u0.x, wb2); ffma2(acc[5], u0.y, wb2);
            ffma2(acc[6], u1.x, wb2); ffma2(acc[7], u1.y, wb2);
        }
        float ba = b1[fp], bbv = b1[fp + 32];
#pragma unroll
        for (int t = 0; t < 4; t++) {
            float a0, a1;
            unpack2(acc[t], a0, a1);
            *(float2*)(sX + fp * 36 + rh * 8 + 2 * t) =
                make_float2(fmaxf(a0 + ba, 0.0f), fmaxf(a1 + ba, 0.0f));
            unpack2(acc[4 + t], a0, a1);
            *(float2*)(sX + (fp + 32) * 36 + rh * 8 + 2 * t) =
                make_float2(fmaxf(a0 + bbv, 0.0f), fmaxf(a1 + bbv, 0.0f));
        }
    }
    __syncthreads();

    // stage 2: 64 -> 128, partial maxpool over 16 rows per thread-group
    {
        const int fp = tid & 63;        // features fp, fp+64
        const int rhh = tid >> 6;       // rows rhh*16 .. +15
        unsigned long long acc[16];
#pragma unroll
        for (int t = 0; t < 16; t++) acc[t] = 0ull;
#pragma unroll 4
        for (int c = 0; c < 64; c++) {
            float wa = w2[c * 128 + fp];
            float wb = w2[c * 128 + fp + 64];
            unsigned long long wa2 = pack2(wa, wa);
            unsigned long long wb2 = pack2(wb, wb);
            const ulonglong2* gp = (const ulonglong2*)(sX + c * 36 + rhh * 16);
            ulonglong2 u0 = gp[0], u1 = gp[1], u2 = gp[2], u3 = gp[3];
            ffma2(acc[0], u0.x, wa2); ffma2(acc[1], u0.y, wa2);
            ffma2(acc[2], u1.x, wa2); ffma2(acc[3], u1.y, wa2);
            ffma2(acc[4], u2.x, wa2); ffma2(acc[5], u2.y, wa2);
            ffma2(acc[6], u3.x, wa2); ffma2(acc[7], u3.y, wa2);
            ffma2(acc[8],  u0.x, wb2); ffma2(acc[9],  u0.y, wb2);
            ffma2(acc[10], u1.x, wb2); ffma2(acc[11], u1.y, wb2);
            ffma2(acc[12], u2.x, wb2); ffma2(acc[13], u2.y, wb2);
            ffma2(acc[14], u3.x, wb2); ffma2(acc[15], u3.y, wb2);
        }
        float ba = b2[fp], bbv = b2[fp + 64];
        float ma = 0.0f, mb = 0.0f;
#pragma unroll
        for (int t = 0; t < 8; t++) {
            float a0, a1;
            unpack2(acc[t], a0, a1);
            ma = fmaxf(ma, fmaxf(a0 + ba, 0.0f));
            ma = fmaxf(ma, fmaxf(a1 + ba, 0.0f));
            unpack2(acc[8 + t], a0, a1);
            mb = fmaxf(mb, fmaxf(a0 + bbv, 0.0f));
            mb = fmaxf(mb, fmaxf(a1 + bbv, 0.0f));
        }
        smax[rhh][fp] = ma;
        smax[rhh][fp + 64] = mb;
    }
    __syncthreads();
    {
        float m = fmaxf(smax[0][tid], smax[1][tid]);
        out_points[(size_t)gw * 128 + tid] = m;
    }
}

extern "C" void kernel_launch(void* const* d_in, const int* in_sizes, int n_in,
                              void* d_out, int out_size) {
    const float* xyz = (const float*)d_in[0];
    const float* points = (const float*)d_in[1];
    const float* w0 = (const float*)d_in[2];
    const float* b0 = (const float*)d_in[3];
    const float* w1 = (const float*)d_in[4];
    const float* b1 = (const float*)d_in[5];
    const float* w2 = (const float*)d_in[6];
    const float* b2 = (const float*)d_in[7];

    float* out = (float*)d_out;
    float* new_xyz = out;                   // [B, S, 3]
    float* new_points = out + BB * SS * 3;  // [B, S, 128]

    fps_kernel<<<BB, 256>>>(xyz, new_xyz);
    qb_kernel<<<(BB * SS * 32 + 255) / 256, 256>>>(xyz, new_xyz);
    mlp_kernel<<<BB * SS, 128>>>(xyz, points, new_xyz,
                                 w0, b0, w1, b1, w2, b2, new_points);
}